// round 12
// baseline (speedup 1.0000x reference)
#include <cuda_runtime.h>

// LSTMNet: 3-layer LSTM (H=6, input=1), B=8192, T=512, FC head on final h2.
// Round 12: R11 (205.9us champion: tanh.approx cell, doubled-h folding) +
// R7 layer-wavefront: iteration n runs l2(n-2); l1(n-1); l0(n) as three
// INDEPENDENT chains. R11 is latency-bound (issue 46.6%, path ~390cyc/step);
// wavefront cuts the critical path to ~1 layer (~130cyc) with zero extra
// live registers (R7-verified: regs stay 168).

#define HD 6
#define TT 512
#define PK 164                 // floats per lane-k slice; 656B stride, conflict-free
#define WPB 12
#define TPB (WPB * 32)
__device__ float g_packk[6 * PK];

// per-k slice layout (floats):
//   0: b0[4] (i,f,g,o)   4: wx0[4]   8+4j: Whh0 col j
//  32: b1   36+4j: Wih1 col j   60+4j: Whh1 col j
//  84: b2   88+4j: Wih2 col j  112+4j: Whh2 col j
// 136: fc_w[k] (pre-halved)  137: fc_b
// scales: rows i,f,o: z/2 form -> x0.5 ; row g: x1.0.
// h-consuming weights additionally x0.5 (stored h is 2h).

__global__ void prep_kernel(
    const float* __restrict__ Wih0, const float* __restrict__ Whh0,
    const float* __restrict__ bih0, const float* __restrict__ bhh0,
    const float* __restrict__ Wih1, const float* __restrict__ Whh1,
    const float* __restrict__ bih1, const float* __restrict__ bhh1,
    const float* __restrict__ Wih2, const float* __restrict__ Whh2,
    const float* __restrict__ bih2, const float* __restrict__ bhh2,
    const float* __restrict__ fcw, const float* __restrict__ fcb)
{
    int tid = threadIdx.x;
    if (tid < 24) {
        int k = tid / 4, g = tid % 4;
        float s  = (g == 2) ? 1.0f : 0.5f;    // pre-activation scale
        float sh = s * 0.5f;                  // + compensation for doubled h
        int row = g * HD + k;                 // PyTorch gate order i,f,g,o
        float* p = g_packk + k * PK;
        p[0 + g]  = (bih0[row] + bhh0[row]) * s;
        p[4 + g]  = Wih0[row] * s;            // x input (not doubled)
        p[32 + g] = (bih1[row] + bhh1[row]) * s;
        p[84 + g] = (bih2[row] + bhh2[row]) * s;
        for (int j = 0; j < HD; j++) {
            p[8   + j * 4 + g] = Whh0[row * HD + j] * sh;
            p[36  + j * 4 + g] = Wih1[row * HD + j] * sh;
            p[60  + j * 4 + g] = Whh1[row * HD + j] * sh;
            p[88  + j * 4 + g] = Wih2[row * HD + j] * sh;
            p[112 + j * 4 + g] = Whh2[row * HD + j] * sh;
        }
    }
    if (tid < 6) {
        g_packk[tid * PK + 136] = fcw[tid] * 0.5f;   // consumes doubled h2
        g_packk[tid * PK + 137] = fcb[0];
    }
}

typedef unsigned long long ull;

// ---- f32x2 + fast-math primitives ----
__device__ __forceinline__ void fma2(ull& d, ull a, ull b, ull c) {
    asm("fma.rn.f32x2 %0, %1, %2, %3;" : "=l"(d) : "l"(a), "l"(b), "l"(c));
}
__device__ __forceinline__ void mul2(ull& d, ull a, ull b) {
    asm("mul.rn.f32x2 %0, %1, %2;" : "=l"(d) : "l"(a), "l"(b));
}
__device__ __forceinline__ void add2(ull& d, ull a, ull b) {
    asm("add.rn.f32x2 %0, %1, %2;" : "=l"(d) : "l"(a), "l"(b));
}
__device__ __forceinline__ ull pack2(float x, float y) {
    ull d; asm("mov.b64 %0, {%1, %2};" : "=l"(d) : "f"(x), "f"(y)); return d;
}
__device__ __forceinline__ void unpack2(float& x, float& y, ull v) {
    asm("mov.b64 {%0, %1}, %2;" : "=f"(x), "=f"(y) : "l"(v));
}
__device__ __forceinline__ float tanh_ap(float x) {
    float y; asm("tanh.approx.f32 %0, %1;" : "=f"(y) : "f"(x)); return y;
}

// aif = (zi/2, zf/2), ago = (zg, zo/2)  [h-doubling already folded in weights]
// outputs: c (true cell state), h2x = 2*h (doubled hidden, consumers pre-halved)
__device__ __forceinline__ void cell(ull aif, ull ago, float& c, float& h2x) {
    float ai, af, ag, ao;
    unpack2(ai, af, aif);
    unpack2(ag, ao, ago);
    float ti = tanh_ap(ai);
    float tf = tanh_ap(af);
    float tg = tanh_ap(ag);
    float to = tanh_ap(ao);
    float A  = fmaf(tf, c, c);        // (1+tf)*c   = 2f*c
    float Bv = fmaf(ti, tg, tg);      // (1+ti)*tg  = 2i*g
    c = (A + Bv) * 0.5f;
    float th = tanh_ap(c);
    h2x = fmaf(to, th, th);           // (1+to)*th  = 2*o*tanh(c) = 2h
}

// 12-col matvec (6 input cols + 6 recurrent cols), 2 independent chains.
__device__ __forceinline__ void matvec12(const ulonglong2* __restrict__ w2,
                                         const float vin[HD], const float vrec[HD],
                                         ull bif, ull bgo, ull& aif, ull& ago)
{
    ull a0, a1, b0, b1;
    {   ulonglong2 w = w2[0];
        ull vv = pack2(vin[0], vin[0]);
        fma2(a0, w.x, vv, bif);
        fma2(a1, w.y, vv, bgo); }
#pragma unroll
    for (int j = 1; j < HD; j++) {
        ulonglong2 w = w2[j];
        ull vv = pack2(vin[j], vin[j]);
        fma2(a0, w.x, vv, a0);
        fma2(a1, w.y, vv, a1);
    }
    {   ulonglong2 w = w2[6];
        ull vv = pack2(vrec[0], vrec[0]);
        mul2(b0, w.x, vv);
        mul2(b1, w.y, vv); }
#pragma unroll
    for (int j = 1; j < HD; j++) {
        ulonglong2 w = w2[6 + j];
        ull vv = pack2(vrec[j], vrec[j]);
        fma2(b0, w.x, vv, b0);
        fma2(b1, w.y, vv, b1);
    }
    add2(aif, a0, b0);
    add2(ago, a1, b1);
}

__global__ void __launch_bounds__(TPB, 1)
lstm6_kernel(const float* __restrict__ x, float* __restrict__ out, int B)
{
    __shared__ __align__(16) float sw[6 * PK];
    for (int i = threadIdx.x; i < 6 * PK; i += TPB) sw[i] = g_packk[i];
    __syncthreads();

    int wid  = blockIdx.x * WPB + (threadIdx.x >> 5);
    int lane = threadIdx.x & 31;
    if (wid * 5 >= B) return;                       // warp-uniform exit

    int sub = lane / HD;                            // 0..4 active, 5 = spare
    int k   = lane - sub * HD;
    int sb  = (sub < 5) ? sub * HD : 0;             // shuffle base
    int elem = wid * 5 + (sub < 5 ? sub : 0);
    bool store_ok = (sub < 5) && (elem < B) && (k == 0);
    if (elem >= B) elem = B - 1;                    // clamp loads only

    const float* pk = sw + k * PK;
    const ull* pk8 = reinterpret_cast<const ull*>(pk);

    // hoist biases + layer-0 x-weights + fc only (R5/R11-proven reg budget)
    ull b0if = pk8[0],  b0go = pk8[1];
    ull wxif = pk8[2],  wxgo = pk8[3];
    ull b1if = pk8[16], b1go = pk8[17];
    ull b2if = pk8[42], b2go = pk8[43];
    float fcwk = pk[136], fcbv = pk[137];

    const ulonglong2* w0c = reinterpret_cast<const ulonglong2*>(pk8 + 4);  // 6 cols
    const ulonglong2* w1c = reinterpret_cast<const ulonglong2*>(pk8 + 18); // 12 cols
    const ulonglong2* w2c = reinterpret_cast<const ulonglong2*>(pk8 + 44); // 12 cols

    const float4* xp = reinterpret_cast<const float4*>(x + (size_t)elem * TT);

    float h0v[HD], h1v[HD], h2v[HD];
    float c0 = 0.f, c1 = 0.f, c2 = 0.f, h2own = 0.f;
#pragma unroll
    for (int j = 0; j < HD; j++) h0v[j] = h1v[j] = h2v[j] = 0.f;

    // ---- layer step macros (R11 math, R7 wavefront scheduling) ----
#define L0STEP(xt)                                                     \
    {   ull xx = pack2((xt), (xt));                                    \
        ull a0_, a1_, q0_, q1_, aif_, ago_;                            \
        fma2(a0_, wxif, xx, b0if);                                     \
        fma2(a1_, wxgo, xx, b0go);                                     \
        _Pragma("unroll")                                              \
        for (int j = 0; j < 3; j++) {                                  \
            ulonglong2 w = w0c[j];                                     \
            ull vv = pack2(h0v[j], h0v[j]);                            \
            fma2(a0_, w.x, vv, a0_);                                   \
            fma2(a1_, w.y, vv, a1_);                                   \
        }                                                              \
        {   ulonglong2 w = w0c[3];                                     \
            ull vv = pack2(h0v[3], h0v[3]);                            \
            mul2(q0_, w.x, vv);                                        \
            mul2(q1_, w.y, vv); }                                      \
        _Pragma("unroll")                                              \
        for (int j = 4; j < HD; j++) {                                 \
            ulonglong2 w = w0c[j];                                     \
            ull vv = pack2(h0v[j], h0v[j]);                            \
            fma2(q0_, w.x, vv, q0_);                                   \
            fma2(q1_, w.y, vv, q1_);                                   \
        }                                                              \
        add2(aif_, a0_, q0_);                                          \
        add2(ago_, a1_, q1_);                                          \
        float hn_;                                                     \
        cell(aif_, ago_, c0, hn_);                                     \
        _Pragma("unroll")                                              \
        for (int j = 0; j < HD; j++)                                   \
            h0v[j] = __shfl_sync(0xffffffffu, hn_, sb + j);            \
    }

#define L1STEP()                                                       \
    {   ull aif_, ago_; float hn_;                                     \
        matvec12(w1c, h0v, h1v, b1if, b1go, aif_, ago_);               \
        cell(aif_, ago_, c1, hn_);                                     \
        _Pragma("unroll")                                              \
        for (int j = 0; j < HD; j++)                                   \
            h1v[j] = __shfl_sync(0xffffffffu, hn_, sb + j);            \
    }

#define L2STEP()                                                       \
    {   ull aif_, ago_;                                                \
        matvec12(w2c, h1v, h2v, b2if, b2go, aif_, ago_);               \
        cell(aif_, ago_, c2, h2own);                                   \
        _Pragma("unroll")                                              \
        for (int j = 0; j < HD; j++)                                   \
            h2v[j] = __shfl_sync(0xffffffffu, h2own, sb + j);          \
    }

    // ---- wavefront fill (iterations n=0..3, x(0..3)) ----
    {
        float4 xq = __ldg(xp);
        L0STEP(xq.x);                       // n=0: l0(0)
        L1STEP(); L0STEP(xq.y);             // n=1: l1(0), l0(1)
        L2STEP(); L1STEP(); L0STEP(xq.z);   // n=2: l2(0), l1(1), l0(2)
        L2STEP(); L1STEP(); L0STEP(xq.w);   // n=3: l2(1), l1(2), l0(3)
    }

    // ---- main wavefront loop: iteration n runs l2(n-2), l1(n-1), l0(n) ----
    // the three chains are independent within an iteration: L2 reads h1v
    // before L1 overwrites it; L1 reads h0v before L0 overwrites it.
#pragma unroll 1
    for (int t4 = 1; t4 < TT / 4; t4++) {
        float4 xq = __ldg(xp + t4);
        L2STEP(); L1STEP(); L0STEP(xq.x);
        L2STEP(); L1STEP(); L0STEP(xq.y);
        L2STEP(); L1STEP(); L0STEP(xq.z);
        L2STEP(); L1STEP(); L0STEP(xq.w);
    }

    // ---- drain: l2(510), l1(511), then l2(511) ----
    L2STEP(); L1STEP();
    L2STEP();

    // FC head: out[e] = sum_k (2h2[k])*(fc_w[k]/2) + fc_b
    float r = h2own * fcwk;
    float s = fcbv;
#pragma unroll
    for (int j = 0; j < HD; j++)
        s += __shfl_sync(0xffffffffu, r, sb + j);
    if (store_ok) out[elem] = s;

#undef L0STEP
#undef L1STEP
#undef L2STEP
}

extern "C" void kernel_launch(void* const* d_in, const int* in_sizes, int n_in,
                              void* d_out, int out_size)
{
    const float* x = (const float*)d_in[0];
    int B = in_sizes[0] / TT;                  // 8192
    int warps  = (B + 4) / 5;                  // 1639
    int blocks = (warps + WPB - 1) / WPB;      // 137

    prep_kernel<<<1, 64>>>(
        (const float*)d_in[1],  (const float*)d_in[2],
        (const float*)d_in[3],  (const float*)d_in[4],
        (const float*)d_in[5],  (const float*)d_in[6],
        (const float*)d_in[7],  (const float*)d_in[8],
        (const float*)d_in[9],  (const float*)d_in[10],
        (const float*)d_in[11], (const float*)d_in[12],
        (const float*)d_in[13], (const float*)d_in[14]);

    lstm6_kernel<<<blocks, TPB>>>(x, (float*)d_out, B);
}

// round 13
// speedup vs baseline: 1.0861x; 1.0861x over previous
#include <cuda_runtime.h>

// LSTMNet: 3-layer LSTM (H=6, input=1), B=8192, T=512, FC head on final h2.
// Round 13: R11 (205.9us champion) + WARP PHASE-STAGGERING.
// R11 analysis: step ~900cyc = fma-busy(438) + MUFU-busy(360) SERIALIZED --
// the 3 warps per SMSP run phase-locked (identical code, same start), so fma
// bursts (matvec) and MUFU bursts (tanh cell) alternate instead of overlap.
// Fix: one-time per-warp delay prologue (0/~350/~700 cyc by warp position on
// the SMSP) desynchronizes the phases; the offset persists (no syncs in loop).
// Kernel math is byte-identical to R11.

#define HD 6
#define TT 512
#define PK 164                 // floats per lane-k slice; 656B stride, conflict-free
#define WPB 12
#define TPB (WPB * 32)
__device__ float g_packk[6 * PK];

// per-k slice layout (floats):
//   0: b0[4] (i,f,g,o)   4: wx0[4]   8+4j: Whh0 col j
//  32: b1   36+4j: Wih1 col j   60+4j: Whh1 col j
//  84: b2   88+4j: Wih2 col j  112+4j: Whh2 col j
// 136: fc_w[k] (pre-halved)  137: fc_b
// scales: rows i,f,o: z/2 form -> x0.5 ; row g: x1.0.
// h-consuming weights additionally x0.5 (stored h is 2h).

__global__ void prep_kernel(
    const float* __restrict__ Wih0, const float* __restrict__ Whh0,
    const float* __restrict__ bih0, const float* __restrict__ bhh0,
    const float* __restrict__ Wih1, const float* __restrict__ Whh1,
    const float* __restrict__ bih1, const float* __restrict__ bhh1,
    const float* __restrict__ Wih2, const float* __restrict__ Whh2,
    const float* __restrict__ bih2, const float* __restrict__ bhh2,
    const float* __restrict__ fcw, const float* __restrict__ fcb)
{
    int tid = threadIdx.x;
    if (tid < 24) {
        int k = tid / 4, g = tid % 4;
        float s  = (g == 2) ? 1.0f : 0.5f;    // pre-activation scale
        float sh = s * 0.5f;                  // + compensation for doubled h
        int row = g * HD + k;                 // PyTorch gate order i,f,g,o
        float* p = g_packk + k * PK;
        p[0 + g]  = (bih0[row] + bhh0[row]) * s;
        p[4 + g]  = Wih0[row] * s;            // x input (not doubled)
        p[32 + g] = (bih1[row] + bhh1[row]) * s;
        p[84 + g] = (bih2[row] + bhh2[row]) * s;
        for (int j = 0; j < HD; j++) {
            p[8   + j * 4 + g] = Whh0[row * HD + j] * sh;
            p[36  + j * 4 + g] = Wih1[row * HD + j] * sh;
            p[60  + j * 4 + g] = Whh1[row * HD + j] * sh;
            p[88  + j * 4 + g] = Wih2[row * HD + j] * sh;
            p[112 + j * 4 + g] = Whh2[row * HD + j] * sh;
        }
    }
    if (tid < 6) {
        g_packk[tid * PK + 136] = fcw[tid] * 0.5f;   // consumes doubled h2
        g_packk[tid * PK + 137] = fcb[0];
    }
}

typedef unsigned long long ull;

// ---- f32x2 + fast-math primitives ----
__device__ __forceinline__ void fma2(ull& d, ull a, ull b, ull c) {
    asm("fma.rn.f32x2 %0, %1, %2, %3;" : "=l"(d) : "l"(a), "l"(b), "l"(c));
}
__device__ __forceinline__ void mul2(ull& d, ull a, ull b) {
    asm("mul.rn.f32x2 %0, %1, %2;" : "=l"(d) : "l"(a), "l"(b));
}
__device__ __forceinline__ void add2(ull& d, ull a, ull b) {
    asm("add.rn.f32x2 %0, %1, %2;" : "=l"(d) : "l"(a), "l"(b));
}
__device__ __forceinline__ ull pack2(float x, float y) {
    ull d; asm("mov.b64 %0, {%1, %2};" : "=l"(d) : "f"(x), "f"(y)); return d;
}
__device__ __forceinline__ void unpack2(float& x, float& y, ull v) {
    asm("mov.b64 {%0, %1}, %2;" : "=f"(x), "=f"(y) : "l"(v));
}
__device__ __forceinline__ float tanh_ap(float x) {
    float y; asm("tanh.approx.f32 %0, %1;" : "=f"(y) : "f"(x)); return y;
}

// aif = (zi/2, zf/2), ago = (zg, zo/2)  [h-doubling already folded in weights]
// outputs: c (true cell state), h2x = 2*h (doubled hidden, consumers pre-halved)
__device__ __forceinline__ void cell(ull aif, ull ago, float& c, float& h2x) {
    float ai, af, ag, ao;
    unpack2(ai, af, aif);
    unpack2(ag, ao, ago);
    float ti = tanh_ap(ai);
    float tf = tanh_ap(af);
    float tg = tanh_ap(ag);
    float to = tanh_ap(ao);
    float A  = fmaf(tf, c, c);        // (1+tf)*c   = 2f*c
    float Bv = fmaf(ti, tg, tg);      // (1+ti)*tg  = 2i*g
    c = (A + Bv) * 0.5f;
    float th = tanh_ap(c);
    h2x = fmaf(to, th, th);           // (1+to)*th  = 2*o*tanh(c) = 2h
}

// 12-col matvec (6 input cols + 6 recurrent cols), 2 independent chains.
__device__ __forceinline__ void matvec12(const ulonglong2* __restrict__ w2,
                                         const float vin[HD], const float vrec[HD],
                                         ull bif, ull bgo, ull& aif, ull& ago)
{
    ull a0, a1, b0, b1;
    {   ulonglong2 w = w2[0];
        ull vv = pack2(vin[0], vin[0]);
        fma2(a0, w.x, vv, bif);
        fma2(a1, w.y, vv, bgo); }
#pragma unroll
    for (int j = 1; j < HD; j++) {
        ulonglong2 w = w2[j];
        ull vv = pack2(vin[j], vin[j]);
        fma2(a0, w.x, vv, a0);
        fma2(a1, w.y, vv, a1);
    }
    {   ulonglong2 w = w2[6];
        ull vv = pack2(vrec[0], vrec[0]);
        mul2(b0, w.x, vv);
        mul2(b1, w.y, vv); }
#pragma unroll
    for (int j = 1; j < HD; j++) {
        ulonglong2 w = w2[6 + j];
        ull vv = pack2(vrec[j], vrec[j]);
        fma2(b0, w.x, vv, b0);
        fma2(b1, w.y, vv, b1);
    }
    add2(aif, a0, b0);
    add2(ago, a1, b1);
}

__global__ void __launch_bounds__(TPB, 1)
lstm6_kernel(const float* __restrict__ x, float* __restrict__ out, int B)
{
    __shared__ __align__(16) float sw[6 * PK];
    for (int i = threadIdx.x; i < 6 * PK; i += TPB) sw[i] = g_packk[i];
    __syncthreads();

    int wid  = blockIdx.x * WPB + (threadIdx.x >> 5);
    int lane = threadIdx.x & 31;
    if (wid * 5 >= B) return;                       // warp-uniform exit

    // ---- phase-stagger: desynchronize the 3 warps sharing each SMSP ----
    // SMSP = wid_local % 4; the 3 warps on it are wid_local>>2 = 0,1,2.
    // delay ~= phase * 44 iters * ~8cyc ~= 0 / 350 / 700 cycles, one-time.
    {
        int phase = ((threadIdx.x >> 5) >> 2);      // 0,1,2 for WPB=12
        float d = 1.0f;
#pragma unroll 1
        for (int i = 0; i < phase * 44; i++) {
            asm volatile("fma.rn.f32 %0, %0, 0f3F800001, 0f3727C5AC;" : "+f"(d));
        }
        // d intentionally unused; asm volatile prevents elimination.
    }

    int sub = lane / HD;                            // 0..4 active, 5 = spare
    int k   = lane - sub * HD;
    int sb  = (sub < 5) ? sub * HD : 0;             // shuffle base
    int elem = wid * 5 + (sub < 5 ? sub : 0);
    bool store_ok = (sub < 5) && (elem < B) && (k == 0);
    if (elem >= B) elem = B - 1;                    // clamp loads only

    const float* pk = sw + k * PK;
    const ull* pk8 = reinterpret_cast<const ull*>(pk);

    // hoist biases + layer-0 x-weights + fc only (R5/R11-proven reg budget)
    ull b0if = pk8[0],  b0go = pk8[1];
    ull wxif = pk8[2],  wxgo = pk8[3];
    ull b1if = pk8[16], b1go = pk8[17];
    ull b2if = pk8[42], b2go = pk8[43];
    float fcwk = pk[136], fcbv = pk[137];

    const ulonglong2* w0c = reinterpret_cast<const ulonglong2*>(pk8 + 4);  // 6 cols
    const ulonglong2* w1c = reinterpret_cast<const ulonglong2*>(pk8 + 18); // 12 cols
    const ulonglong2* w2c = reinterpret_cast<const ulonglong2*>(pk8 + 44); // 12 cols

    const float4* xp = reinterpret_cast<const float4*>(x + (size_t)elem * TT);

    float h0v[HD], h1v[HD], h2v[HD];
    float c0 = 0.f, c1 = 0.f, c2 = 0.f, h2own = 0.f;
#pragma unroll
    for (int j = 0; j < HD; j++) h0v[j] = h1v[j] = h2v[j] = 0.f;

#pragma unroll 1
    for (int t4 = 0; t4 < TT / 4; t4++) {
        float4 xq = __ldg(xp + t4);
#pragma unroll
        for (int u = 0; u < 4; u++) {
            float xt = (u == 0) ? xq.x : (u == 1) ? xq.y : (u == 2) ? xq.z : xq.w;

            // ---- layer 0: b0 + wx*x + Whh0 @ h0v (2 chains) ----
            ull xx = pack2(xt, xt);
            ull a0, a1, q0, q1, aif, ago;
            fma2(a0, wxif, xx, b0if);
            fma2(a1, wxgo, xx, b0go);
#pragma unroll
            for (int j = 0; j < 3; j++) {
                ulonglong2 w = w0c[j];
                ull vv = pack2(h0v[j], h0v[j]);
                fma2(a0, w.x, vv, a0);
                fma2(a1, w.y, vv, a1);
            }
            {   ulonglong2 w = w0c[3];
                ull vv = pack2(h0v[3], h0v[3]);
                mul2(q0, w.x, vv);
                mul2(q1, w.y, vv); }
#pragma unroll
            for (int j = 4; j < HD; j++) {
                ulonglong2 w = w0c[j];
                ull vv = pack2(h0v[j], h0v[j]);
                fma2(q0, w.x, vv, q0);
                fma2(q1, w.y, vv, q1);
            }
            add2(aif, a0, q0);
            add2(ago, a1, q1);
            float h0n;
            cell(aif, ago, c0, h0n);
#pragma unroll
            for (int j = 0; j < HD; j++)
                h0v[j] = __shfl_sync(0xffffffffu, h0n, sb + j);

            // ---- layer 1 ----
            float h1n;
            matvec12(w1c, h0v, h1v, b1if, b1go, aif, ago);
            cell(aif, ago, c1, h1n);
#pragma unroll
            for (int j = 0; j < HD; j++)
                h1v[j] = __shfl_sync(0xffffffffu, h1n, sb + j);

            // ---- layer 2 ----
            matvec12(w2c, h1v, h2v, b2if, b2go, aif, ago);
            cell(aif, ago, c2, h2own);
#pragma unroll
            for (int j = 0; j < HD; j++)
                h2v[j] = __shfl_sync(0xffffffffu, h2own, sb + j);
        }
    }

    // FC head: out[e] = sum_k (2h2[k])*(fc_w[k]/2) + fc_b
    float r = h2own * fcwk;
    float s = fcbv;
#pragma unroll
    for (int j = 0; j < HD; j++)
        s += __shfl_sync(0xffffffffu, r, sb + j);
    if (store_ok) out[elem] = s;
}

extern "C" void kernel_launch(void* const* d_in, const int* in_sizes, int n_in,
                              void* d_out, int out_size)
{
    const float* x = (const float*)d_in[0];
    int B = in_sizes[0] / TT;                  // 8192
    int warps  = (B + 4) / 5;                  // 1639
    int blocks = (warps + WPB - 1) / WPB;      // 137

    prep_kernel<<<1, 64>>>(
        (const float*)d_in[1],  (const float*)d_in[2],
        (const float*)d_in[3],  (const float*)d_in[4],
        (const float*)d_in[5],  (const float*)d_in[6],
        (const float*)d_in[7],  (const float*)d_in[8],
        (const float*)d_in[9],  (const float*)d_in[10],
        (const float*)d_in[11], (const float*)d_in[12],
        (const float*)d_in[13], (const float*)d_in[14]);

    lstm6_kernel<<<blocks, TPB>>>(x, (float*)d_out, B);
}